// round 16
// baseline (speedup 1.0000x reference)
#include <cuda_runtime.h>
#include <cuda_bf16.h>
#include <cstdint>
#include <math.h>

// AFM: y[b] = fc_b + fc_w . sum_p softmax_p( w2 . relu(W1^T (x_i*x_j) + b1) ) * (x_i*x_j)
// One CTA per batch row.
// R16: R14 tiling restored (1 mtile x 8 ntiles per warp -- R15's (2,4) retile
//      regressed: issue 46.8->37.4, latency-bound) + the orthogonal R15 trims:
//      uint4 Bfrag (one LDS.128 for bh|bl) and STS.128 buildA stores.

#define NF      32
#define EMB     64
#define NPAIR   496
#define XPAD    68
#define THREADS 256
#define MH      128            // rows per quarter
#define NQ      4
#define ABYTES_ROW 272         // 136 bf16: 16B-aligned, 4-bank offset per row

// phase-2 structures inside the A region (valid after last quarter)
#define SROW     40            // S row stride in elements (80 B, 16B-aligned rows)
#define SH_OFF   0             // uint16 Sh[32][40]  (2560 B)
#define SL_OFF   2560          // uint16 Sl[32][40]  (2560 B)
#define XFH_OFF  5120          // uint2  Xfh[2][8][32] (4096 B)
#define XFL_OFF  9216          // uint2  Xfl[2][8][32] (4096 B)

__device__ uint4 g_Bfrag[4][8][32];   // [ks][ntile][lane] = (Whi.x, Whi.y, Wlo.x, Wlo.y)

struct Smem {
    char  A[MH * ABYTES_ROW];        // 34816  A quarter | phase-2 region (Sh/Sl/Xfrag)
    uint4 Bfrag[4][8][32];           // 16384
    float Xs[NF * XPAD];             // 8704
    float z[2 * EMB];                // (b1[a], w2[a]) interleaved
    float score[NPAIR];              // 1984
    uint32_t offs[NPAIR];            // 1984   (ci*XPAD) | (cj*XPAD)<<16  (word offsets)
    float fcw[EMB];
    float fp2[2 * EMB];              // 512    phase-2 partials (per mi-half)
    float red[8];
    float smax, sinv;
};

__device__ __forceinline__ uint32_t pack_bf16x2(__nv_bfloat16 l, __nv_bfloat16 h) {
    return (uint32_t)__bfloat16_as_ushort(l) | ((uint32_t)__bfloat16_as_ushort(h) << 16);
}

// packed pair (lo=a, hi=b) -> bf16x2 in one cvt
__device__ __forceinline__ uint32_t cvt2_bf16(float lo, float hi) {
    uint32_t r;
    asm("cvt.rn.bf16x2.f32 %0, %1, %2;" : "=r"(r) : "f"(hi), "f"(lo));
    return r;
}

__device__ __forceinline__ void mma16816(float* d, const uint32_t* a, uint32_t b0, uint32_t b1) {
    asm volatile(
        "mma.sync.aligned.m16n8k16.row.col.f32.bf16.bf16.f32 "
        "{%0,%1,%2,%3}, {%4,%5,%6,%7}, {%8,%9}, {%0,%1,%2,%3};"
        : "+f"(d[0]), "+f"(d[1]), "+f"(d[2]), "+f"(d[3])
        : "r"(a[0]), "r"(a[1]), "r"(a[2]), "r"(a[3]), "r"(b0), "r"(b1));
}

// A fragment (m16k16) from the C buffer, row stride ABYTES_ROW
__device__ __forceinline__ void lda(uint32_t* a, uint32_t Abase, int rbase, int k0, int lane) {
    int mat = lane >> 3, r8 = lane & 7;
    int row = rbase + r8 + ((mat & 1) << 3);
    int col = k0 + ((mat >> 1) << 3);
    uint32_t addr = Abase + (uint32_t)(row * ABYTES_ROW + col * 2);
    asm volatile("ldmatrix.sync.aligned.m8n8.x4.shared.b16 {%0,%1,%2,%3}, [%4];"
                 : "=r"(a[0]), "=r"(a[1]), "=r"(a[2]), "=r"(a[3]) : "r"(addr));
}

// A fragment (m16k16) from the S matrix, row stride SROW*2 = 80 B (16B-aligned rows)
__device__ __forceinline__ void lda_s(uint32_t* a, uint32_t Sbase, int mi, int ks, int lane) {
    int mat = lane >> 3, r8 = lane & 7;
    int row = 16 * mi + r8 + ((mat & 1) << 3);
    int col = 16 * ks + ((mat >> 1) << 3);
    uint32_t addr = Sbase + (uint32_t)(row * (SROW * 2) + col * 2);
    asm volatile("ldmatrix.sync.aligned.m8n8.x4.shared.b16 {%0,%1,%2,%3}, [%4];"
                 : "=r"(a[0]), "=r"(a[1]), "=r"(a[2]), "=r"(a[3]) : "r"(addr));
}

// ---- one-time chip-wide B-fragment build (batch-invariant) ----
__global__ void bfrag_prep(const float* __restrict__ w1) {
    int tid = threadIdx.x;
    for (int e = tid; e < 4 * 8 * 32; e += 256) {
        int ln = e & 31, n = (e >> 5) & 7, ks = e >> 8;
        int c = ln & 3, g = ln >> 2;
        int a = n * 8 + g;
        int d0 = ks * 16 + 2 * c;
        float f0 = w1[(d0)     * EMB + a];
        float f1 = w1[(d0 + 1) * EMB + a];
        float f2 = w1[(d0 + 8) * EMB + a];
        float f3 = w1[(d0 + 9) * EMB + a];
        __nv_bfloat16 h0 = __float2bfloat16_rn(f0), h1 = __float2bfloat16_rn(f1);
        __nv_bfloat16 h2 = __float2bfloat16_rn(f2), h3 = __float2bfloat16_rn(f3);
        __nv_bfloat16 l0 = __float2bfloat16_rn(f0 - __bfloat162float(h0));
        __nv_bfloat16 l1 = __float2bfloat16_rn(f1 - __bfloat162float(h1));
        __nv_bfloat16 l2 = __float2bfloat16_rn(f2 - __bfloat162float(h2));
        __nv_bfloat16 l3 = __float2bfloat16_rn(f3 - __bfloat162float(h3));
        g_Bfrag[ks][n][ln] = make_uint4(pack_bf16x2(h0, h1), pack_bf16x2(h2, h3),
                                        pack_bf16x2(l0, l1), pack_bf16x2(l2, l3));
    }
}

__global__ __launch_bounds__(THREADS, 3)
void afm_kernel(const float* __restrict__ x,
                const float* __restrict__ b1,
                const float* __restrict__ w2,
                const float* __restrict__ fcw,
                const float* __restrict__ fcb,
                float* __restrict__ out)
{
    extern __shared__ __align__(16) char smem_raw[];
    Smem* S = (Smem*)smem_raw;
    uint32_t Abase;
    asm("{ .reg .u64 t; cvta.to.shared.u64 t, %1; cvt.u32.u64 %0, t; }"
        : "=r"(Abase) : "l"(S->A));

    const int tid  = threadIdx.x;
    const int b    = blockIdx.x;
    const int lane = tid & 31;
    const int warp = tid >> 5;

    // ---- cooperative loads ----
    const float* xb = x + (size_t)b * (NF * EMB);
    for (int idx = tid; idx < NF * EMB; idx += THREADS)
        S->Xs[(idx >> 6) * XPAD + (idx & 63)] = xb[idx];

    if (tid < EMB) {
        S->z[2 * tid] = b1[tid];
        S->z[2 * tid + 1] = w2[tid];
        S->fcw[tid] = fcw[tid];
    }

    // copy precomputed B fragments (gmem -> smem, L2-resident after wave 1)
    {
        const uint4* src = (const uint4*)g_Bfrag;
        uint4* dst = (uint4*)S->Bfrag;
        #pragma unroll
        for (int i = 0; i < 4; i++) dst[tid + i * THREADS] = src[tid + i * THREADS];
    }

    // pair offsets via closed-form triu index: row i starts at i*(63-i)/2
    for (int p = tid; p < NPAIR; p += THREADS) {
        float t = sqrtf((float)(3969 - 8 * p));
        int i = (int)((63.0f - t) * 0.5f);
        while ((i + 1) * (63 - (i + 1)) / 2 <= p) i++;   // <=2 fixup steps
        while (i * (63 - i) / 2 > p) i--;
        int j = i + 1 + (p - i * (63 - i) / 2);
        S->offs[p] = (uint32_t)(i * XPAD) | ((uint32_t)(j * XPAD) << 16);
    }
    __syncthreads();

    // ---- four quarters of 128 pair-rows ----
    for (int qt = 0; qt < NQ; qt++) {
        // build A quarter: row r, cols 0-63 = hi(C), 64-127 = lo(C); STS.128 stores
        for (int idx = tid; idx < MH * 8; idx += THREADS) {
            int ch2 = idx & 7, r = idx >> 3;        // ch2: 8-dim chunk
            int p = qt * MH + r;
            char* row = S->A + r * ABYTES_ROW;
            if (p < NPAIR) {
                uint32_t o = S->offs[p];
                const float* xi = S->Xs + (o & 0xFFFFu) + 8 * ch2;
                const float* xj = S->Xs + (o >> 16) + 8 * ch2;
                float4 ai0 = *(const float4*)xi;
                float4 ai1 = *(const float4*)(xi + 4);
                float4 aj0 = *(const float4*)xj;
                float4 aj1 = *(const float4*)(xj + 4);
                float c0 = ai0.x * aj0.x, c1 = ai0.y * aj0.y;
                float c2 = ai0.z * aj0.z, c3 = ai0.w * aj0.w;
                float c4 = ai1.x * aj1.x, c5 = ai1.y * aj1.y;
                float c6 = ai1.z * aj1.z, c7 = ai1.w * aj1.w;
                uint32_t h01 = cvt2_bf16(c0, c1), h23 = cvt2_bf16(c2, c3);
                uint32_t h45 = cvt2_bf16(c4, c5), h67 = cvt2_bf16(c6, c7);
                float r0 = __uint_as_float(h01 << 16), r1 = __uint_as_float(h01 & 0xFFFF0000u);
                float r2 = __uint_as_float(h23 << 16), r3 = __uint_as_float(h23 & 0xFFFF0000u);
                float r4 = __uint_as_float(h45 << 16), r5 = __uint_as_float(h45 & 0xFFFF0000u);
                float r6 = __uint_as_float(h67 << 16), r7 = __uint_as_float(h67 & 0xFFFF0000u);
                *(uint4*)(row + 16 * ch2) = make_uint4(h01, h23, h45, h67);
                *(uint4*)(row + 128 + 16 * ch2) =
                    make_uint4(cvt2_bf16(c0 - r0, c1 - r1), cvt2_bf16(c2 - r2, c3 - r3),
                               cvt2_bf16(c4 - r4, c5 - r5), cvt2_bf16(c6 - r6, c7 - r7));
            } else {
                *(uint4*)(row + 16 * ch2)       = make_uint4(0u, 0u, 0u, 0u);
                *(uint4*)(row + 128 + 16 * ch2) = make_uint4(0u, 0u, 0u, 0u);
            }
        }
        __syncthreads();

        // MMA: warp owns one 16-row m-tile, flat n 0..7
        const int rb = warp * 16;
        const int c = lane & 3, g = lane >> 2;
        float d[8][4];
        #pragma unroll
        for (int n = 0; n < 8; n++)
            #pragma unroll
            for (int q = 0; q < 4; q++) d[n][q] = 0.f;

        #pragma unroll
        for (int ks = 0; ks < 4; ks++) {
            uint32_t ah[4], al[4];
            lda(ah, Abase, rb, 16 * ks, lane);        // A_hi
            lda(al, Abase, rb, 64 + 16 * ks, lane);   // A_lo
            #pragma unroll
            for (int n = 0; n < 8; n++) {
                uint4 bb = S->Bfrag[ks][n][lane];     // one LDS.128: (Whi, Wlo)
                mma16816(d[n], ah, bb.x, bb.y);       // C_hi * W_hi
                mma16816(d[n], ah, bb.z, bb.w);       // C_hi * W_lo
                mma16816(d[n], al, bb.x, bb.y);       // C_lo * W_hi
            }
        }

        float ps0 = 0.f, ps1 = 0.f;
        #pragma unroll
        for (int n = 0; n < 8; n++) {
            float4 zz = *(const float4*)&S->z[2 * (8 * n + 2 * c)];  // b1/w2 for 2 cols
            ps0 += fmaxf(d[n][0] + zz.x, 0.f) * zz.y
                 + fmaxf(d[n][1] + zz.z, 0.f) * zz.w;
            ps1 += fmaxf(d[n][2] + zz.x, 0.f) * zz.y
                 + fmaxf(d[n][3] + zz.z, 0.f) * zz.w;
        }

        #pragma unroll
        for (int off = 1; off <= 2; off <<= 1) {
            ps0 += __shfl_xor_sync(0xFFFFFFFFu, ps0, off);
            ps1 += __shfl_xor_sync(0xFFFFFFFFu, ps1, off);
        }
        if (c == 0) {
            int p0 = qt * MH + rb + g;
            if (p0 < NPAIR)     S->score[p0]     = ps0;
            if (p0 + 8 < NPAIR) S->score[p0 + 8] = ps1;
        }
        __syncthreads();   // A consumed by all warps; safe to rebuild
    }

    // ---- softmax over 496 pairs ----
    float m = -INFINITY;
    for (int p = tid; p < NPAIR; p += THREADS) m = fmaxf(m, S->score[p]);
    #pragma unroll
    for (int o = 16; o; o >>= 1) m = fmaxf(m, __shfl_xor_sync(0xFFFFFFFFu, m, o));
    if (lane == 0) S->red[warp] = m;
    __syncthreads();
    if (tid == 0) {
        float mm = S->red[0];
        #pragma unroll
        for (int k = 1; k < 8; k++) mm = fmaxf(mm, S->red[k]);
        S->smax = mm;
    }
    __syncthreads();
    const float mm = S->smax;

    float lsum = 0.f;
    for (int p = tid; p < NPAIR; p += THREADS) {
        float e = __expf(S->score[p] - mm);
        S->score[p] = e;
        lsum += e;
    }
    #pragma unroll
    for (int o = 16; o; o >>= 1) lsum += __shfl_xor_sync(0xFFFFFFFFu, lsum, o);
    if (lane == 0) S->red[warp] = lsum;
    __syncthreads();
    if (tid == 0) {
        float ss = 0.f;
        #pragma unroll
        for (int k = 0; k < 8; k++) ss += S->red[k];
        S->sinv = 1.0f / ss;
    }
    __syncthreads();
    const float inv = S->sinv;

    // ---- phase 2: f = 0.5 * diag(X^T (S X)),  T = S X via 3-product bf16 MMA ----
    uint16_t* Sh = (uint16_t*)(S->A + SH_OFF);
    uint16_t* Sl = (uint16_t*)(S->A + SL_OFF);
    uint2 (*Xfh)[8][32] = (uint2 (*)[8][32])(S->A + XFH_OFF);
    uint2 (*Xfl)[8][32] = (uint2 (*)[8][32])(S->A + XFL_OFF);

    // zero S diagonal; padding cols (32..39) never read by lda_s (ks<=1 -> cols<32)
    if (tid < NF) { Sh[tid * SROW + tid] = 0; Sl[tid * SROW + tid] = 0; }

    // scatter exp-scores into symmetric S (hi/lo bf16)
    for (int p = tid; p < NPAIR; p += THREADS) {
        float s = S->score[p];
        uint32_t o = S->offs[p];
        int i = (int)(o & 0xFFFFu) / XPAD;
        int j = (int)(o >> 16) / XPAD;
        __nv_bfloat16 hb = __float2bfloat16_rn(s);
        float hf = __bfloat162float(hb);
        __nv_bfloat16 lb = __float2bfloat16_rn(s - hf);
        uint16_t hu = __bfloat16_as_ushort(hb), lu = __bfloat16_as_ushort(lb);
        Sh[i * SROW + j] = hu; Sh[j * SROW + i] = hu;
        Sl[i * SROW + j] = lu; Sl[j * SROW + i] = lu;
    }

    // build X fragments (B operand of m16n8k16): lane t -> n_col = 8n+(t>>2), k rows j0=16ks+2(t&3)
    for (int e = tid; e < 2 * 8 * 32; e += THREADS) {
        int t = e & 31, n = (e >> 5) & 7, ks = e >> 8;
        int dcol = 8 * n + (t >> 2);
        int j0 = 16 * ks + 2 * (t & 3);
        float v00 = S->Xs[j0 * XPAD + dcol];
        float v01 = S->Xs[(j0 + 1) * XPAD + dcol];
        float v10 = S->Xs[(j0 + 8) * XPAD + dcol];
        float v11 = S->Xs[(j0 + 9) * XPAD + dcol];
        uint32_t h0 = cvt2_bf16(v00, v01);
        uint32_t h1 = cvt2_bf16(v10, v11);
        float r00 = __uint_as_float(h0 << 16), r01 = __uint_as_float(h0 & 0xFFFF0000u);
        float r10 = __uint_as_float(h1 << 16), r11 = __uint_as_float(h1 & 0xFFFF0000u);
        Xfh[ks][n][t] = make_uint2(h0, h1);
        Xfl[ks][n][t] = make_uint2(cvt2_bf16(v00 - r00, v01 - r01),
                                   cvt2_bf16(v10 - r10, v11 - r11));
    }
    __syncthreads();

    // T = S X: warp w -> mi = w&1 (rows 16mi..+16), n-tiles {w>>1, (w>>1)+4}
    {
        const int mi = warp & 1, nb = warp >> 1;
        const int c = lane & 3, g = lane >> 2;
        uint32_t sh[2][4], sl[2][4];
        uint32_t ShB = Abase + SH_OFF, SlB = Abase + SL_OFF;
        lda_s(sh[0], ShB, mi, 0, lane); lda_s(sh[1], ShB, mi, 1, lane);
        lda_s(sl[0], SlB, mi, 0, lane); lda_s(sl[1], SlB, mi, 1, lane);

        #pragma unroll
        for (int u = 0; u < 2; u++) {
            int n = nb + 4 * u;
            float t[4] = {0.f, 0.f, 0.f, 0.f};
            #pragma unroll
            for (int ks = 0; ks < 2; ks++) {
                uint2 bh = Xfh[ks][n][lane];
                uint2 bl = Xfl[ks][n][lane];
                mma16816(t, sh[ks], bh.x, bh.y);   // S_hi * X_hi
                mma16816(t, sl[ks], bh.x, bh.y);   // S_lo * X_hi
                mma16816(t, sh[ks], bl.x, bl.y);   // S_hi * X_lo
            }
            // fold: partial_d = sum_i X[i][d] * T[i][d] over this warp's rows
            int i0 = 16 * mi + g, i1 = i0 + 8;
            int d0 = 8 * n + 2 * c, d1 = d0 + 1;
            float p0 = S->Xs[i0 * XPAD + d0] * t[0] + S->Xs[i1 * XPAD + d0] * t[2];
            float p1 = S->Xs[i0 * XPAD + d1] * t[1] + S->Xs[i1 * XPAD + d1] * t[3];
            #pragma unroll
            for (int off = 4; off <= 16; off <<= 1) {     // reduce over g (lane bits 2-4)
                p0 += __shfl_xor_sync(0xFFFFFFFFu, p0, off);
                p1 += __shfl_xor_sync(0xFFFFFFFFu, p1, off);
            }
            if (g == 0) {
                S->fp2[mi * EMB + d0] = p0;
                S->fp2[mi * EMB + d1] = p1;
            }
        }
    }
    __syncthreads();

    if (tid < EMB) {
        float f = (S->fp2[tid] + S->fp2[EMB + tid]) * 0.5f * inv * S->fcw[tid];
        S->fp2[tid] = f;
    }
    __syncthreads();
    if (tid == 0) {
        float y = fcb[0];
        #pragma unroll
        for (int k = 0; k < EMB; k++) y += S->fp2[k];
        out[b] = y;
    }
}

extern "C" void kernel_launch(void* const* d_in, const int* in_sizes, int n_in,
                              void* d_out, int out_size)
{
    const float* x   = (const float*)d_in[0];
    const float* w1  = (const float*)d_in[1];
    const float* b1  = (const float*)d_in[2];
    const float* w2  = (const float*)d_in[3];
    const float* fcw = (const float*)d_in[4];
    const float* fcb = (const float*)d_in[5];
    float* out = (float*)d_out;

    static int smem_set = -1;
    const int smem_bytes = (int)sizeof(Smem);
    if (smem_set != smem_bytes) {
        cudaFuncSetAttribute(afm_kernel, cudaFuncAttributeMaxDynamicSharedMemorySize, smem_bytes);
        smem_set = smem_bytes;
    }

    const int batch = out_size;   // NUM_CLASSES = 1
    bfrag_prep<<<1, 256>>>(w1);                                      // batch-invariant B fragments
    afm_kernel<<<batch, THREADS, smem_bytes>>>(x, b1, w2, fcw, fcb, out);
}

// round 17
// speedup vs baseline: 1.0853x; 1.0853x over previous
#include <cuda_runtime.h>
#include <cuda_bf16.h>
#include <cstdint>
#include <math.h>

// AFM: y[b] = fc_b + fc_w . sum_p softmax_p( w2 . relu(W1^T (x_i*x_j) + b1) ) * (x_i*x_j)
// One CTA per batch row.
// R17: R14 exactly (uint2 Bfrag + uint2 buildA stores -- the R15/R16 uint4/STS.128
//      "trims" both regressed by starving issue) with ONE change: buildA made
//      warp-local (warp w builds exactly its own A rows [16w,16w+16)), so the
//      4-quarter score loop runs with NO CTA-wide barriers (one __syncwarp per
//      quarter instead of 2 __syncthreads). Warps skew/pipeline freely.

#define NF      32
#define EMB     64
#define NPAIR   496
#define XPAD    68
#define THREADS 256
#define MH      128            // rows per quarter
#define NQ      4
#define ABYTES_ROW 272         // 136 bf16: 16B-aligned, 4-bank offset per row

// phase-2 structures inside the A region (valid after last quarter)
#define SROW     40            // S row stride in elements (80 B, 16B-aligned rows)
#define SH_OFF   0             // uint16 Sh[32][40]  (2560 B)
#define SL_OFF   2560          // uint16 Sl[32][40]  (2560 B)
#define XFH_OFF  5120          // uint2  Xfh[2][8][32] (4096 B)
#define XFL_OFF  9216          // uint2  Xfl[2][8][32] (4096 B)

__device__ uint2 g_Bfrag[8][8][32];   // [src*4+ks][ntile][lane]; src0=W_hi, src1=W_lo

struct Smem {
    char  A[MH * ABYTES_ROW];        // 34816  A quarter | phase-2 region (Sh/Sl/Xfrag)
    uint2 Bfrag[8][8][32];           // 16384
    float Xs[NF * XPAD];             // 8704
    float z[2 * EMB];                // (b1[a], w2[a]) interleaved
    float score[NPAIR];              // 1984
    uint32_t offs[NPAIR];            // 1984   (ci*XPAD) | (cj*XPAD)<<16  (word offsets)
    float fcw[EMB];
    float fp2[2 * EMB];              // 512    phase-2 partials (per mi-half)
    float red[8];
    float smax, sinv;
};

__device__ __forceinline__ uint32_t pack_bf16x2(__nv_bfloat16 l, __nv_bfloat16 h) {
    return (uint32_t)__bfloat16_as_ushort(l) | ((uint32_t)__bfloat16_as_ushort(h) << 16);
}

// packed pair (lo=a, hi=b) -> bf16x2 in one cvt
__device__ __forceinline__ uint32_t cvt2_bf16(float lo, float hi) {
    uint32_t r;
    asm("cvt.rn.bf16x2.f32 %0, %1, %2;" : "=r"(r) : "f"(hi), "f"(lo));
    return r;
}

__device__ __forceinline__ void mma16816(float* d, const uint32_t* a, uint2 b) {
    asm volatile(
        "mma.sync.aligned.m16n8k16.row.col.f32.bf16.bf16.f32 "
        "{%0,%1,%2,%3}, {%4,%5,%6,%7}, {%8,%9}, {%0,%1,%2,%3};"
        : "+f"(d[0]), "+f"(d[1]), "+f"(d[2]), "+f"(d[3])
        : "r"(a[0]), "r"(a[1]), "r"(a[2]), "r"(a[3]), "r"(b.x), "r"(b.y));
}

// A fragment (m16k16) from the C buffer, row stride ABYTES_ROW
__device__ __forceinline__ void lda(uint32_t* a, uint32_t Abase, int rbase, int k0, int lane) {
    int mat = lane >> 3, r8 = lane & 7;
    int row = rbase + r8 + ((mat & 1) << 3);
    int col = k0 + ((mat >> 1) << 3);
    uint32_t addr = Abase + (uint32_t)(row * ABYTES_ROW + col * 2);
    asm volatile("ldmatrix.sync.aligned.m8n8.x4.shared.b16 {%0,%1,%2,%3}, [%4];"
                 : "=r"(a[0]), "=r"(a[1]), "=r"(a[2]), "=r"(a[3]) : "r"(addr));
}

// A fragment (m16k16) from the S matrix, row stride SROW*2 = 80 B (16B-aligned rows)
__device__ __forceinline__ void lda_s(uint32_t* a, uint32_t Sbase, int mi, int ks, int lane) {
    int mat = lane >> 3, r8 = lane & 7;
    int row = 16 * mi + r8 + ((mat & 1) << 3);
    int col = 16 * ks + ((mat >> 1) << 3);
    uint32_t addr = Sbase + (uint32_t)(row * (SROW * 2) + col * 2);
    asm volatile("ldmatrix.sync.aligned.m8n8.x4.shared.b16 {%0,%1,%2,%3}, [%4];"
                 : "=r"(a[0]), "=r"(a[1]), "=r"(a[2]), "=r"(a[3]) : "r"(addr));
}

// ---- one-time chip-wide B-fragment build (batch-invariant) ----
__global__ void bfrag_prep(const float* __restrict__ w1) {
    int tid = threadIdx.x;
    for (int e = tid; e < 8 * 8 * 32; e += 256) {
        int ln = e & 31, n = (e >> 5) & 7, sk = e >> 8;   // sk = src*4 + ks4
        int src = sk >> 2, k4 = sk & 3;
        int c = ln & 3, g = ln >> 2;
        int a = n * 8 + g;
        int d0 = k4 * 16 + 2 * c;
        float f0 = w1[(d0)     * EMB + a];
        float f1 = w1[(d0 + 1) * EMB + a];
        float f2 = w1[(d0 + 8) * EMB + a];
        float f3 = w1[(d0 + 9) * EMB + a];
        __nv_bfloat16 h0 = __float2bfloat16_rn(f0), h1 = __float2bfloat16_rn(f1);
        __nv_bfloat16 h2 = __float2bfloat16_rn(f2), h3 = __float2bfloat16_rn(f3);
        __nv_bfloat16 v0, v1, v2, v3;
        if (src == 0) { v0 = h0; v1 = h1; v2 = h2; v3 = h3; }
        else {
            v0 = __float2bfloat16_rn(f0 - __bfloat162float(h0));
            v1 = __float2bfloat16_rn(f1 - __bfloat162float(h1));
            v2 = __float2bfloat16_rn(f2 - __bfloat162float(h2));
            v3 = __float2bfloat16_rn(f3 - __bfloat162float(h3));
        }
        g_Bfrag[sk][n][ln] = make_uint2(pack_bf16x2(v0, v1), pack_bf16x2(v2, v3));
    }
}

__global__ __launch_bounds__(THREADS, 3)
void afm_kernel(const float* __restrict__ x,
                const float* __restrict__ b1,
                const float* __restrict__ w2,
                const float* __restrict__ fcw,
                const float* __restrict__ fcb,
                float* __restrict__ out)
{
    extern __shared__ __align__(16) char smem_raw[];
    Smem* S = (Smem*)smem_raw;
    uint32_t Abase;
    asm("{ .reg .u64 t; cvta.to.shared.u64 t, %1; cvt.u32.u64 %0, t; }"
        : "=r"(Abase) : "l"(S->A));

    const int tid  = threadIdx.x;
    const int b    = blockIdx.x;
    const int lane = tid & 31;
    const int warp = tid >> 5;

    // ---- cooperative loads ----
    const float* xb = x + (size_t)b * (NF * EMB);
    for (int idx = tid; idx < NF * EMB; idx += THREADS)
        S->Xs[(idx >> 6) * XPAD + (idx & 63)] = xb[idx];

    if (tid < EMB) {
        S->z[2 * tid] = b1[tid];
        S->z[2 * tid + 1] = w2[tid];
        S->fcw[tid] = fcw[tid];
    }

    // copy precomputed B fragments (gmem -> smem, L2-resident after wave 1)
    {
        const uint2* src = (const uint2*)g_Bfrag;
        uint2* dst = (uint2*)S->Bfrag;
        #pragma unroll
        for (int i = 0; i < 8; i++) dst[tid + i * THREADS] = src[tid + i * THREADS];
    }

    // pair offsets via closed-form triu index: row i starts at i*(63-i)/2
    for (int p = tid; p < NPAIR; p += THREADS) {
        float t = sqrtf((float)(3969 - 8 * p));
        int i = (int)((63.0f - t) * 0.5f);
        while ((i + 1) * (63 - (i + 1)) / 2 <= p) i++;   // <=2 fixup steps
        while (i * (63 - i) / 2 > p) i--;
        int j = i + 1 + (p - i * (63 - i) / 2);
        S->offs[p] = (uint32_t)(i * XPAD) | ((uint32_t)(j * XPAD) << 16);
    }
    __syncthreads();

    // ---- four quarters of 128 pair-rows; NO CTA barriers inside the loop ----
    // Warp w builds and consumes ONLY A rows [16w, 16w+16) -> warp-local pipeline.
    const int rb = warp * 16;
    const int c = lane & 3, g = lane >> 2;

    for (int qt = 0; qt < NQ; qt++) {
        // build this warp's 16 A rows: row r, cols 0-63 = hi(C), 64-127 = lo(C)
        #pragma unroll
        for (int it = lane; it < 16 * 16; it += 32) {
            int ch = it & 15, rr = it >> 4;
            int r = rb + rr;
            int p = qt * MH + r;
            char* row = S->A + r * ABYTES_ROW;
            if (p < NPAIR) {
                uint32_t o = S->offs[p];
                const float* xi = S->Xs + (o & 0xFFFFu) + 4 * ch;
                const float* xj = S->Xs + (o >> 16) + 4 * ch;
                float4 a4 = *(const float4*)xi;
                float4 c4 = *(const float4*)xj;
                float c0 = a4.x * c4.x, c1 = a4.y * c4.y, c2 = a4.z * c4.z, c3 = a4.w * c4.w;
                uint32_t hi01 = cvt2_bf16(c0, c1);
                uint32_t hi23 = cvt2_bf16(c2, c3);
                float r0 = __uint_as_float(hi01 << 16);
                float r1 = __uint_as_float(hi01 & 0xFFFF0000u);
                float r2 = __uint_as_float(hi23 << 16);
                float r3 = __uint_as_float(hi23 & 0xFFFF0000u);
                uint32_t lo01 = cvt2_bf16(c0 - r0, c1 - r1);
                uint32_t lo23 = cvt2_bf16(c2 - r2, c3 - r3);
                *(uint2*)(row + 8 * ch)       = make_uint2(hi01, hi23);
                *(uint2*)(row + 128 + 8 * ch) = make_uint2(lo01, lo23);
            } else {
                *(uint2*)(row + 8 * ch)       = make_uint2(0u, 0u);
                *(uint2*)(row + 128 + 8 * ch) = make_uint2(0u, 0u);
            }
        }
        __syncwarp();    // this warp's A rows visible to its own ldmatrix

        // MMA: flat n 0..7 over this warp's m-tile
        float d[8][4];
        #pragma unroll
        for (int n = 0; n < 8; n++)
            #pragma unroll
            for (int q = 0; q < 4; q++) d[n][q] = 0.f;

        #pragma unroll
        for (int ks = 0; ks < 4; ks++) {
            uint32_t ah[4], al[4];
            lda(ah, Abase, rb, 16 * ks, lane);        // A_hi
            lda(al, Abase, rb, 64 + 16 * ks, lane);   // A_lo
            #pragma unroll
            for (int n = 0; n < 8; n++) {
                uint2 bh = S->Bfrag[ks][n][lane];
                uint2 bl = S->Bfrag[4 + ks][n][lane];
                mma16816(d[n], ah, bh);   // C_hi * W_hi
                mma16816(d[n], ah, bl);   // C_hi * W_lo
                mma16816(d[n], al, bh);   // C_lo * W_hi
            }
        }

        float ps0 = 0.f, ps1 = 0.f;
        #pragma unroll
        for (int n = 0; n < 8; n++) {
            float4 zz = *(const float4*)&S->z[2 * (8 * n + 2 * c)];  // b1/w2 for 2 cols
            ps0 += fmaxf(d[n][0] + zz.x, 0.f) * zz.y
                 + fmaxf(d[n][1] + zz.z, 0.f) * zz.w;
            ps1 += fmaxf(d[n][2] + zz.x, 0.f) * zz.y
                 + fmaxf(d[n][3] + zz.z, 0.f) * zz.w;
        }

        #pragma unroll
        for (int off = 1; off <= 2; off <<= 1) {
            ps0 += __shfl_xor_sync(0xFFFFFFFFu, ps0, off);
            ps1 += __shfl_xor_sync(0xFFFFFFFFu, ps1, off);
        }
        if (c == 0) {
            int p0 = qt * MH + rb + g;
            if (p0 < NPAIR)     S->score[p0]     = ps0;
            if (p0 + 8 < NPAIR) S->score[p0 + 8] = ps1;
        }
        // no barrier: next buildA touches only this warp's rows, already consumed
    }
    __syncthreads();   // all warps' scores visible before softmax

    // ---- softmax over 496 pairs ----
    float m = -INFINITY;
    for (int p = tid; p < NPAIR; p += THREADS) m = fmaxf(m, S->score[p]);
    #pragma unroll
    for (int o = 16; o; o >>= 1) m = fmaxf(m, __shfl_xor_sync(0xFFFFFFFFu, m, o));
    if (lane == 0) S->red[warp] = m;
    __syncthreads();
    if (tid == 0) {
        float mm = S->red[0];
        #pragma unroll
        for (int k = 1; k < 8; k++) mm = fmaxf(mm, S->red[k]);
        S->smax = mm;
    }
    __syncthreads();
    const float mm = S->smax;

    float lsum = 0.f;
    for (int p = tid; p < NPAIR; p += THREADS) {
        float e = __expf(S->score[p] - mm);
        S->score[p] = e;
        lsum += e;
    }
    #pragma unroll
    for (int o = 16; o; o >>= 1) lsum += __shfl_xor_sync(0xFFFFFFFFu, lsum, o);
    if (lane == 0) S->red[warp] = lsum;
    __syncthreads();
    if (tid == 0) {
        float ss = 0.f;
        #pragma unroll
        for (int k = 0; k < 8; k++) ss += S->red[k];
        S->sinv = 1.0f / ss;
    }
    __syncthreads();
    const float inv = S->sinv;

    // ---- phase 2: f = 0.5 * diag(X^T (S X)),  T = S X via 3-product bf16 MMA ----
    uint16_t* Sh = (uint16_t*)(S->A + SH_OFF);
    uint16_t* Sl = (uint16_t*)(S->A + SL_OFF);
    uint2 (*Xfh)[8][32] = (uint2 (*)[8][32])(S->A + XFH_OFF);
    uint2 (*Xfl)[8][32] = (uint2 (*)[8][32])(S->A + XFL_OFF);

    // zero S diagonal; padding cols (32..39) never read by lda_s (ks<=1 -> cols<32)
    if (tid < NF) { Sh[tid * SROW + tid] = 0; Sl[tid * SROW + tid] = 0; }

    // scatter exp-scores into symmetric S (hi/lo bf16)
    for (int p = tid; p < NPAIR; p += THREADS) {
        float s = S->score[p];
        uint32_t o = S->offs[p];
        int i = (int)(o & 0xFFFFu) / XPAD;
        int j = (int)(o >> 16) / XPAD;
        __nv_bfloat16 hb = __float2bfloat16_rn(s);
        float hf = __bfloat162float(hb);
        __nv_bfloat16 lb = __float2bfloat16_rn(s - hf);
        uint16_t hu = __bfloat16_as_ushort(hb), lu = __bfloat16_as_ushort(lb);
        Sh[i * SROW + j] = hu; Sh[j * SROW + i] = hu;
        Sl[i * SROW + j] = lu; Sl[j * SROW + i] = lu;
    }

    // build X fragments (B operand of m16n8k16): lane t -> n_col = 8n+(t>>2), k rows j0=16ks+2(t&3)
    for (int e = tid; e < 2 * 8 * 32; e += THREADS) {
        int t = e & 31, n = (e >> 5) & 7, ks = e >> 8;
        int dcol = 8 * n + (t >> 2);
        int j0 = 16 * ks + 2 * (t & 3);
        float v00 = S->Xs[j0 * XPAD + dcol];
        float v01 = S->Xs[(j0 + 1) * XPAD + dcol];
        float v10 = S->Xs[(j0 + 8) * XPAD + dcol];
        float v11 = S->Xs[(j0 + 9) * XPAD + dcol];
        uint32_t h0 = cvt2_bf16(v00, v01);
        uint32_t h1 = cvt2_bf16(v10, v11);
        float r00 = __uint_as_float(h0 << 16), r01 = __uint_as_float(h0 & 0xFFFF0000u);
        float r10 = __uint_as_float(h1 << 16), r11 = __uint_as_float(h1 & 0xFFFF0000u);
        Xfh[ks][n][t] = make_uint2(h0, h1);
        Xfl[ks][n][t] = make_uint2(cvt2_bf16(v00 - r00, v01 - r01),
                                   cvt2_bf16(v10 - r10, v11 - r11));
    }
    __syncthreads();

    // T = S X: warp w -> mi = w&1 (rows 16mi..+16), n-tiles {w>>1, (w>>1)+4}
    {
        const int mi = warp & 1, nb = warp >> 1;
        uint32_t sh[2][4], sl[2][4];
        uint32_t ShB = Abase + SH_OFF, SlB = Abase + SL_OFF;
        lda_s(sh[0], ShB, mi, 0, lane); lda_s(sh[1], ShB, mi, 1, lane);
        lda_s(sl[0], SlB, mi, 0, lane); lda_s(sl[1], SlB, mi, 1, lane);

        #pragma unroll
        for (int u = 0; u < 2; u++) {
            int n = nb + 4 * u;
            float t[4] = {0.f, 0.f, 0.f, 0.f};
            #pragma unroll
            for (int ks = 0; ks < 2; ks++) {
                uint2 bh = Xfh[ks][n][lane];
                uint2 bl = Xfl[ks][n][lane];
                mma16816(t, sh[ks], bh);   // S_hi * X_hi
                mma16816(t, sl[ks], bh);   // S_lo * X_hi
                mma16816(t, sh[ks], bl);   // S_hi * X_lo
            }
            // fold: partial_d = sum_i X[i][d] * T[i][d] over this warp's rows
            int i0 = 16 * mi + g, i1 = i0 + 8;
            int d0 = 8 * n + 2 * c, d1 = d0 + 1;
            float p0 = S->Xs[i0 * XPAD + d0] * t[0] + S->Xs[i1 * XPAD + d0] * t[2];
            float p1 = S->Xs[i0 * XPAD + d1] * t[1] + S->Xs[i1 * XPAD + d1] * t[3];
            #pragma unroll
            for (int off = 4; off <= 16; off <<= 1) {     // reduce over g (lane bits 2-4)
                p0 += __shfl_xor_sync(0xFFFFFFFFu, p0, off);
                p1 += __shfl_xor_sync(0xFFFFFFFFu, p1, off);
            }
            if (g == 0) {
                S->fp2[mi * EMB + d0] = p0;
                S->fp2[mi * EMB + d1] = p1;
            }
        }
    }
    __syncthreads();

    if (tid < EMB) {
        float f = (S->fp2[tid] + S->fp2[EMB + tid]) * 0.5f * inv * S->fcw[tid];
        S->fp2[tid] = f;
    }
    __syncthreads();
    if (tid == 0) {
        float y = fcb[0];
        #pragma unroll
        for (int k = 0; k < EMB; k++) y += S->fp2[k];
        out[b] = y;
    }
}

extern "C" void kernel_launch(void* const* d_in, const int* in_sizes, int n_in,
                              void* d_out, int out_size)
{
    const float* x   = (const float*)d_in[0];
    const float* w1  = (const float*)d_in[1];
    const float* b1  = (const float*)d_in[2];
    const float* w2  = (const float*)d_in[3];
    const float* fcw = (const float*)d_in[4];
    const float* fcb = (const float*)d_in[5];
    float* out = (float*)d_out;

    static int smem_set = -1;
    const int smem_bytes = (int)sizeof(Smem);
    if (smem_set != smem_bytes) {
        cudaFuncSetAttribute(afm_kernel, cudaFuncAttributeMaxDynamicSharedMemorySize, smem_bytes);
        smem_set = smem_bytes;
    }

    const int batch = out_size;   // NUM_CLASSES = 1
    bfrag_prep<<<1, 256>>>(w1);                                      // batch-invariant B fragments
    afm_kernel<<<batch, THREADS, smem_bytes>>>(x, b1, w2, fcw, fcb, out);
}